// round 2
// baseline (speedup 1.0000x reference)
#include <cuda_runtime.h>
#include <cstdint>

#define N_NODES 10000
#define IN_DIM  256
#define HIDDEN  512
#define OUT_DIM 256
#define N_EDGES 320000

#define BM 128
#define BN 256
#define BK 64
#define ASTRIDE 72     // 64 + 8 pad -> conflict-free A frag loads
#define BSTRIDE 264    // 256 + 8 pad -> conflict-free B frag loads
#define NTHREADS 512

// Scratch: PQ[node][0:512] = x@W1_top, PQ[node][512:1024] = x@W1_bot
__device__ float g_PQ[(size_t)N_NODES * 1024];
// Normalized int32 edge indices: [0:E)=src, [E:2E)=dst
__device__ int g_EI[2 * N_EDGES];

__device__ __forceinline__ float tf32r(float x) {
    float y;
    asm("cvt.rna.tf32.f32 %0, %1;" : "=f"(y) : "f"(x));
    return y;
}

__device__ __forceinline__ void mma8(float c[4],
                                     uint32_t a0, uint32_t a1, uint32_t a2, uint32_t a3,
                                     uint32_t b0, uint32_t b1) {
    asm volatile(
        "mma.sync.aligned.m16n8k8.row.col.f32.tf32.tf32.f32 "
        "{%0,%1,%2,%3}, {%4,%5,%6,%7}, {%8,%9}, {%0,%1,%2,%3};"
        : "+f"(c[0]), "+f"(c[1]), "+f"(c[2]), "+f"(c[3])
        : "r"(a0), "r"(a1), "r"(a2), "r"(a3), "r"(b0), "r"(b1));
}

// ============================================================================
// Prep: normalize edge_index (int64 or int32, detected on device) to int32.
// If int64: odd 32-bit words of the first 64 values are all 0 (vals in [0,1e4)).
// If int32: those words are random edge IDs, essentially never all zero.
// ============================================================================
__global__ void prep_edges(const int* __restrict__ raw)
{
    __shared__ int s_is64;
    if (threadIdx.x == 0) {
        int nz = 0;
        #pragma unroll
        for (int j = 0; j < 64; j++) nz |= raw[2 * j + 1];
        s_is64 = (nz == 0);
    }
    __syncthreads();
    const int is64 = s_is64;
    int i = blockIdx.x * blockDim.x + threadIdx.x;
    if (i < 2 * N_EDGES) {
        g_EI[i] = is64 ? raw[2 * i] : raw[i];
    }
}

// ============================================================================
// Stage 1: PQ[10000, 1024] = x[10000, 256] @ B'[256, 1024]
//   B'[k][n] = W1[k][n] for n < 512, else W1[256+k][n-512]
// ============================================================================
__global__ void __launch_bounds__(NTHREADS, 1)
node_gemm(const float* __restrict__ x, const float* __restrict__ W1)
{
    extern __shared__ float sm[];
    float* As = sm;                    // BM x ASTRIDE
    float* Bs = sm + BM * ASTRIDE;     // BK x BSTRIDE

    const int tid = threadIdx.x;
    const int m0 = blockIdx.x * BM;
    const int n0 = blockIdx.y * BN;    // 0, 256, 512, 768
    const float* Bbase = (n0 < HIDDEN) ? (W1 + n0)
                                       : (W1 + (size_t)IN_DIM * HIDDEN + (n0 - HIDDEN));

    const int lane = tid & 31, warp = tid >> 5;
    const int wm = warp >> 2, wn = warp & 3;   // 4x4 warp grid
    const int g = lane >> 2, tg = lane & 3;

    float acc[2][8][4];
    #pragma unroll
    for (int i = 0; i < 2; i++)
        #pragma unroll
        for (int j = 0; j < 8; j++)
            #pragma unroll
            for (int k = 0; k < 4; k++) acc[i][j][k] = 0.f;

    for (int kc = 0; kc < IN_DIM; kc += BK) {   // 4 chunks
        #pragma unroll
        for (int i = 0; i < 4; i++) {
            int lin = tid + i * NTHREADS;       // 0..2047
            int row = lin >> 4;
            int c4  = lin & 15;
            int r = m0 + row;
            float4 v = make_float4(0.f, 0.f, 0.f, 0.f);
            if (r < N_NODES) {
                float4 t = *(const float4*)(x + (size_t)r * IN_DIM + kc + c4 * 4);
                v.x = tf32r(t.x); v.y = tf32r(t.y); v.z = tf32r(t.z); v.w = tf32r(t.w);
            }
            *(float4*)(As + row * ASTRIDE + c4 * 4) = v;
        }
        #pragma unroll
        for (int i = 0; i < 8; i++) {
            int lin = tid + i * NTHREADS;       // 0..4095
            int bk = lin >> 6;
            int bn = lin & 63;
            float4 w = *(const float4*)(Bbase + (size_t)(kc + bk) * HIDDEN + bn * 4);
            float4 v;
            v.x = tf32r(w.x); v.y = tf32r(w.y); v.z = tf32r(w.z); v.w = tf32r(w.w);
            *(float4*)(Bs + bk * BSTRIDE + bn * 4) = v;
        }
        __syncthreads();

        #pragma unroll
        for (int k8 = 0; k8 < BK / 8; k8++) {
            const int k0 = k8 * 8;
            uint32_t af[2][4];
            #pragma unroll
            for (int mt = 0; mt < 2; mt++) {
                int rb = wm * 32 + mt * 16;
                af[mt][0] = __float_as_uint(As[(rb + g)     * ASTRIDE + k0 + tg]);
                af[mt][1] = __float_as_uint(As[(rb + g + 8) * ASTRIDE + k0 + tg]);
                af[mt][2] = __float_as_uint(As[(rb + g)     * ASTRIDE + k0 + tg + 4]);
                af[mt][3] = __float_as_uint(As[(rb + g + 8) * ASTRIDE + k0 + tg + 4]);
            }
            uint32_t bf[8][2];
            #pragma unroll
            for (int nt = 0; nt < 8; nt++) {
                int cb = wn * 64 + nt * 8;
                bf[nt][0] = __float_as_uint(Bs[(k0 + tg)     * BSTRIDE + cb + g]);
                bf[nt][1] = __float_as_uint(Bs[(k0 + tg + 4) * BSTRIDE + cb + g]);
            }
            #pragma unroll
            for (int mt = 0; mt < 2; mt++)
                #pragma unroll
                for (int nt = 0; nt < 8; nt++)
                    mma8(acc[mt][nt], af[mt][0], af[mt][1], af[mt][2], af[mt][3],
                         bf[nt][0], bf[nt][1]);
        }
        __syncthreads();
    }

    #pragma unroll
    for (int mt = 0; mt < 2; mt++) {
        int rbase = m0 + wm * 32 + mt * 16;
        #pragma unroll
        for (int nt = 0; nt < 8; nt++) {
            int cb = n0 + wn * 64 + nt * 8 + tg * 2;
            int r0 = rbase + g, r1 = rbase + g + 8;
            if (r0 < N_NODES) {
                float2 v; v.x = acc[mt][nt][0]; v.y = acc[mt][nt][1];
                *(float2*)(g_PQ + (size_t)r0 * 1024 + cb) = v;
            }
            if (r1 < N_NODES) {
                float2 v; v.x = acc[mt][nt][2]; v.y = acc[mt][nt][3];
                *(float2*)(g_PQ + (size_t)r1 * 1024 + cb) = v;
            }
        }
    }
}

// ============================================================================
// Stage 2: out[e,:] = relu(P[s[e]] + Q[t[e]] + b1) @ W2 + b2
// Block: 128 edges x 256 outs, K=512 chunked by 64. Gather fused into A load.
// ============================================================================
__global__ void __launch_bounds__(NTHREADS, 1)
edge_mlp2(const float* __restrict__ b1,
          const float* __restrict__ W2, const float* __restrict__ b2,
          float* __restrict__ out)
{
    extern __shared__ float sm[];
    float* As = sm;
    float* Bs = sm + BM * ASTRIDE;
    __shared__ int sI[BM], tI[BM];
    __shared__ float b1s[HIDDEN];
    __shared__ float b2s[OUT_DIM];

    const int tid = threadIdx.x;
    const int m0 = blockIdx.x * BM;

    if (tid < BM) {
        sI[tid] = g_EI[m0 + tid];
        tI[tid] = g_EI[N_EDGES + m0 + tid];
    }
    if (tid < HIDDEN)  b1s[tid] = b1[tid];
    if (tid < OUT_DIM) b2s[tid] = b2[tid];
    __syncthreads();

    const int lane = tid & 31, warp = tid >> 5;
    const int wm = warp >> 2, wn = warp & 3;
    const int g = lane >> 2, tg = lane & 3;

    float acc[2][8][4];
    #pragma unroll
    for (int i = 0; i < 2; i++)
        #pragma unroll
        for (int j = 0; j < 8; j++)
            #pragma unroll
            for (int k = 0; k < 4; k++) acc[i][j][k] = 0.f;

    for (int kc = 0; kc < HIDDEN; kc += BK) {   // 8 chunks
        #pragma unroll
        for (int i = 0; i < 4; i++) {
            int lin = tid + i * NTHREADS;
            int row = lin >> 4;
            int c4  = lin & 15;
            int k = kc + c4 * 4;
            const float4 p = *(const float4*)(g_PQ + (size_t)sI[row] * 1024 + k);
            const float4 q = *(const float4*)(g_PQ + (size_t)tI[row] * 1024 + 512 + k);
            float4 v;
            v.x = tf32r(fmaxf(p.x + q.x + b1s[k + 0], 0.f));
            v.y = tf32r(fmaxf(p.y + q.y + b1s[k + 1], 0.f));
            v.z = tf32r(fmaxf(p.z + q.z + b1s[k + 2], 0.f));
            v.w = tf32r(fmaxf(p.w + q.w + b1s[k + 3], 0.f));
            *(float4*)(As + row * ASTRIDE + c4 * 4) = v;
        }
        #pragma unroll
        for (int i = 0; i < 8; i++) {
            int lin = tid + i * NTHREADS;
            int bk = lin >> 6;
            int bn = lin & 63;
            float4 w = *(const float4*)(W2 + (size_t)(kc + bk) * OUT_DIM + bn * 4);
            float4 v;
            v.x = tf32r(w.x); v.y = tf32r(w.y); v.z = tf32r(w.z); v.w = tf32r(w.w);
            *(float4*)(Bs + bk * BSTRIDE + bn * 4) = v;
        }
        __syncthreads();

        #pragma unroll
        for (int k8 = 0; k8 < BK / 8; k8++) {
            const int k0 = k8 * 8;
            uint32_t af[2][4];
            #pragma unroll
            for (int mt = 0; mt < 2; mt++) {
                int rb = wm * 32 + mt * 16;
                af[mt][0] = __float_as_uint(As[(rb + g)     * ASTRIDE + k0 + tg]);
                af[mt][1] = __float_as_uint(As[(rb + g + 8) * ASTRIDE + k0 + tg]);
                af[mt][2] = __float_as_uint(As[(rb + g)     * ASTRIDE + k0 + tg + 4]);
                af[mt][3] = __float_as_uint(As[(rb + g + 8) * ASTRIDE + k0 + tg + 4]);
            }
            uint32_t bf[8][2];
            #pragma unroll
            for (int nt = 0; nt < 8; nt++) {
                int cb = wn * 64 + nt * 8;
                bf[nt][0] = __float_as_uint(Bs[(k0 + tg)     * BSTRIDE + cb + g]);
                bf[nt][1] = __float_as_uint(Bs[(k0 + tg + 4) * BSTRIDE + cb + g]);
            }
            #pragma unroll
            for (int mt = 0; mt < 2; mt++)
                #pragma unroll
                for (int nt = 0; nt < 8; nt++)
                    mma8(acc[mt][nt], af[mt][0], af[mt][1], af[mt][2], af[mt][3],
                         bf[nt][0], bf[nt][1]);
        }
        __syncthreads();
    }

    #pragma unroll
    for (int mt = 0; mt < 2; mt++) {
        int rbase = m0 + wm * 32 + mt * 16;
        #pragma unroll
        for (int nt = 0; nt < 8; nt++) {
            int cb = wn * 64 + nt * 8 + tg * 2;
            float bb0 = b2s[cb], bb1 = b2s[cb + 1];
            float2 v0, v1;
            v0.x = acc[mt][nt][0] + bb0; v0.y = acc[mt][nt][1] + bb1;
            v1.x = acc[mt][nt][2] + bb0; v1.y = acc[mt][nt][3] + bb1;
            *(float2*)(out + (size_t)(rbase + g)     * OUT_DIM + cb) = v0;
            *(float2*)(out + (size_t)(rbase + g + 8) * OUT_DIM + cb) = v1;
        }
    }
}

extern "C" void kernel_launch(void* const* d_in, const int* in_sizes, int n_in,
                              void* d_out, int out_size)
{
    (void)out_size;
    // Identify inputs by unique element counts (robust to metadata ordering).
    const float* x  = (const float*)d_in[0];
    const void*  ei = d_in[1];
    const float* W1 = (const float*)d_in[2];
    const float* b1 = (const float*)d_in[3];
    const float* W2 = (const float*)d_in[4];
    const float* b2 = (const float*)d_in[5];
    for (int i = 0; i < n_in; i++) {
        switch (in_sizes[i]) {
            case N_NODES * IN_DIM:      x  = (const float*)d_in[i]; break;  // 2,560,000
            case 2 * N_EDGES:           ei = d_in[i];               break;  // 640,000
            case 2 * IN_DIM * HIDDEN:   W1 = (const float*)d_in[i]; break;  // 262,144
            case HIDDEN:                b1 = (const float*)d_in[i]; break;  // 512
            case HIDDEN * OUT_DIM:      W2 = (const float*)d_in[i]; break;  // 131,072
            case OUT_DIM:               b2 = (const float*)d_in[i]; break;  // 256
            default: break;
        }
    }
    float* out = (float*)d_out;

    const size_t smem = (size_t)(BM * ASTRIDE + BK * BSTRIDE) * sizeof(float);  // ~104 KB
    cudaFuncSetAttribute(node_gemm, cudaFuncAttributeMaxDynamicSharedMemorySize, (int)smem);
    cudaFuncSetAttribute(edge_mlp2, cudaFuncAttributeMaxDynamicSharedMemorySize, (int)smem);

    prep_edges<<<(2 * N_EDGES + 255) / 256, 256>>>((const int*)ei);

    dim3 grid1((N_NODES + BM - 1) / BM, (2 * HIDDEN) / BN);  // 79 x 4
    node_gemm<<<grid1, NTHREADS, smem>>>(x, W1);

    dim3 grid2(N_EDGES / BM);                                 // 2500
    edge_mlp2<<<grid2, NTHREADS, smem>>>(b1, W2, b2, out);
}

// round 8
// speedup vs baseline: 1.0896x; 1.0896x over previous
#include <cuda_runtime.h>
#include <cstdint>

#define N_NODES 10000
#define IN_DIM  256
#define HIDDEN  512
#define OUT_DIM 256
#define N_EDGES 320000

// ---------------- shared tile params ----------------
#define BM 128
#define BN 256
#define BK1 64
#define ASTRIDE 72      // 64 + 8 pad
#define BSTRIDE 264     // 256 + 8 pad
#define NTHREADS 512

// stage-2 double-buffer layout (floats)
#define A_FLOATS (BM * ASTRIDE)        // 9216
#define B_FLOATS (BK1 * BSTRIDE)       // 16896
#define A_OFF(b) ((b) * A_FLOATS)
#define B_OFF(b) (2 * A_FLOATS + (b) * B_FLOATS)
#define DSMEM2   ((2 * A_FLOATS + 2 * B_FLOATS) * sizeof(float))   // 208896 B

// Scratch
__device__ float g_PQ[(size_t)N_NODES * 1024];   // [node][0:512]=x@W1_top, [512:1024]=x@W1_bot
__device__ int   g_EI[2 * N_EDGES];              // normalized int32 indices
__device__ float g_W2R[HIDDEN * OUT_DIM];        // W2 tf32-rounded, same layout [k][n]

// ---------------- helpers ----------------
__device__ __forceinline__ float tf32r(float x) {
    float y; asm("cvt.rna.tf32.f32 %0, %1;" : "=f"(y) : "f"(x)); return y;
}
__device__ __forceinline__ uint32_t smem_u32(const void* p) {
    uint32_t a; asm("{ .reg .u64 t; cvta.to.shared.u64 t, %1; cvt.u32.u64 %0, t; }" : "=r"(a) : "l"(p));
    return a;
}
__device__ __forceinline__ void cp_async16(void* sdst, const void* gsrc) {
    asm volatile("cp.async.cg.shared.global [%0], [%1], 16;"
                 :: "r"(smem_u32(sdst)), "l"(gsrc) : "memory");
}
#define CP_COMMIT() asm volatile("cp.async.commit_group;" ::: "memory")
#define CP_WAIT0()  asm volatile("cp.async.wait_group 0;"  ::: "memory")

__device__ __forceinline__ void mma8(float c[4],
                                     uint32_t a0, uint32_t a1, uint32_t a2, uint32_t a3,
                                     uint32_t b0, uint32_t b1) {
    asm volatile(
        "mma.sync.aligned.m16n8k8.row.col.f32.tf32.tf32.f32 "
        "{%0,%1,%2,%3}, {%4,%5,%6,%7}, {%8,%9}, {%0,%1,%2,%3};"
        : "+f"(c[0]), "+f"(c[1]), "+f"(c[2]), "+f"(c[3])
        : "r"(a0), "r"(a1), "r"(a2), "r"(a3), "r"(b0), "r"(b1));
}

// MMA over k8 range [k8a, k8b) on given smem buffers (32x64 warp tile, 4x4 warp grid)
__device__ __forceinline__ void mma_half(const float* __restrict__ As,
                                         const float* __restrict__ Bs,
                                         float acc[2][8][4],
                                         int wm, int wn, int g, int tg,
                                         int k8a, int k8b)
{
    #pragma unroll
    for (int k8 = k8a; k8 < k8b; k8++) {
        const int k0 = k8 * 8;
        uint32_t af[2][4];
        #pragma unroll
        for (int mt = 0; mt < 2; mt++) {
            int rb = wm * 32 + mt * 16;
            af[mt][0] = __float_as_uint(As[(rb + g)     * ASTRIDE + k0 + tg]);
            af[mt][1] = __float_as_uint(As[(rb + g + 8) * ASTRIDE + k0 + tg]);
            af[mt][2] = __float_as_uint(As[(rb + g)     * ASTRIDE + k0 + tg + 4]);
            af[mt][3] = __float_as_uint(As[(rb + g + 8) * ASTRIDE + k0 + tg + 4]);
        }
        uint32_t bf[8][2];
        #pragma unroll
        for (int nt = 0; nt < 8; nt++) {
            int cb = wn * 64 + nt * 8;
            bf[nt][0] = __float_as_uint(Bs[(k0 + tg)     * BSTRIDE + cb + g]);
            bf[nt][1] = __float_as_uint(Bs[(k0 + tg + 4) * BSTRIDE + cb + g]);
        }
        #pragma unroll
        for (int mt = 0; mt < 2; mt++)
            #pragma unroll
            for (int nt = 0; nt < 8; nt++)
                mma8(acc[mt][nt], af[mt][0], af[mt][1], af[mt][2], af[mt][3],
                     bf[nt][0], bf[nt][1]);
    }
}

// ============================================================================
// Prep kernels
// ============================================================================
__global__ void prep_edges(const int* __restrict__ raw)
{
    __shared__ int s_is64;
    if (threadIdx.x == 0) {
        int nz = 0;
        #pragma unroll
        for (int j = 0; j < 64; j++) nz |= raw[2 * j + 1];
        s_is64 = (nz == 0);
    }
    __syncthreads();
    const int is64 = s_is64;
    int i = blockIdx.x * blockDim.x + threadIdx.x;
    if (i < 2 * N_EDGES) g_EI[i] = is64 ? raw[2 * i] : raw[i];
}

__global__ void prep_w2(const float* __restrict__ W2)
{
    int i = blockIdx.x * blockDim.x + threadIdx.x;
    if (i < HIDDEN * OUT_DIM) g_W2R[i] = tf32r(W2[i]);
}

// ============================================================================
// Stage 1 (warp-mma, unchanged): PQ = x @ [W1_top | W1_bot]
// ============================================================================
__global__ void __launch_bounds__(NTHREADS, 1)
node_gemm(const float* __restrict__ x, const float* __restrict__ W1)
{
    extern __shared__ float sm[];
    float* As = sm;
    float* Bs = sm + BM * ASTRIDE;

    const int tid = threadIdx.x;
    const int m0 = blockIdx.x * BM;
    const int n0 = blockIdx.y * BN;
    const float* Bbase = (n0 < HIDDEN) ? (W1 + n0)
                                       : (W1 + (size_t)IN_DIM * HIDDEN + (n0 - HIDDEN));

    const int lane = tid & 31, warp = tid >> 5;
    const int wm = warp >> 2, wn = warp & 3;
    const int g = lane >> 2, tg = lane & 3;

    float acc[2][8][4];
    #pragma unroll
    for (int i = 0; i < 2; i++)
        #pragma unroll
        for (int j = 0; j < 8; j++)
            #pragma unroll
            for (int k = 0; k < 4; k++) acc[i][j][k] = 0.f;

    for (int kc = 0; kc < IN_DIM; kc += BK1) {
        #pragma unroll
        for (int i = 0; i < 4; i++) {
            int lin = tid + i * NTHREADS;
            int row = lin >> 4, c4 = lin & 15;
            int r = m0 + row;
            float4 v = make_float4(0.f, 0.f, 0.f, 0.f);
            if (r < N_NODES) {
                float4 t = *(const float4*)(x + (size_t)r * IN_DIM + kc + c4 * 4);
                v.x = tf32r(t.x); v.y = tf32r(t.y); v.z = tf32r(t.z); v.w = tf32r(t.w);
            }
            *(float4*)(As + row * ASTRIDE + c4 * 4) = v;
        }
        #pragma unroll
        for (int i = 0; i < 8; i++) {
            int lin = tid + i * NTHREADS;
            int bk = lin >> 6, bn = lin & 63;
            float4 w = *(const float4*)(Bbase + (size_t)(kc + bk) * HIDDEN + bn * 4);
            float4 v;
            v.x = tf32r(w.x); v.y = tf32r(w.y); v.z = tf32r(w.z); v.w = tf32r(w.w);
            *(float4*)(Bs + bk * BSTRIDE + bn * 4) = v;
        }
        __syncthreads();

        mma_half(As, Bs, acc, wm, wn, g, tg, 0, BK1 / 8);
        __syncthreads();
    }

    #pragma unroll
    for (int mt = 0; mt < 2; mt++) {
        int rbase = m0 + wm * 32 + mt * 16;
        #pragma unroll
        for (int nt = 0; nt < 8; nt++) {
            int cb = n0 + wn * 64 + nt * 8 + tg * 2;
            int r0 = rbase + g, r1 = rbase + g + 8;
            if (r0 < N_NODES) {
                float2 v; v.x = acc[mt][nt][0]; v.y = acc[mt][nt][1];
                *(float2*)(g_PQ + (size_t)r0 * 1024 + cb) = v;
            }
            if (r1 < N_NODES) {
                float2 v; v.x = acc[mt][nt][2]; v.y = acc[mt][nt][3];
                *(float2*)(g_PQ + (size_t)r1 * 1024 + cb) = v;
            }
        }
    }
}

// ============================================================================
// Stage 2 (pipelined warp-mma):
//   out[e,:] = relu(P[s]+Q[t]+b1) @ W2 + b2
// Double-buffered A/B tiles; B via cp.async.cg; A gather prefetched in two
// register waves wrapped around the two MMA halves. One sync per chunk.
// ============================================================================
__global__ void __launch_bounds__(NTHREADS, 1)
edge_mlp2(const float* __restrict__ b1, const float* __restrict__ b2,
          float* __restrict__ out)
{
    extern __shared__ float sm[];
    __shared__ int sI[BM], tI[BM];
    __shared__ float b1s[HIDDEN];
    __shared__ float b2s[OUT_DIM];

    const int tid = threadIdx.x;
    const int m0 = blockIdx.x * BM;

    if (tid < BM) {
        sI[tid] = g_EI[m0 + tid];
        tI[tid] = g_EI[N_EDGES + m0 + tid];
    }
    b1s[tid] = b1[tid];                 // 512 threads == HIDDEN
    if (tid < OUT_DIM) b2s[tid] = b2[tid];
    __syncthreads();

    const int lane = tid & 31, warp = tid >> 5;
    const int wm = warp >> 2, wn = warp & 3;
    const int g = lane >> 2, tg = lane & 3;

    // per-thread gather coordinates (fixed across chunks): iteration i covers
    // lin = tid + i*512 -> row = lin>>4, k-quad = (lin&15)*4
    const int row0 = tid >> 4;          // rows 0..31   (i=0)
    const int kq   = (tid & 15) * 4;    // 0..60

    float acc[2][8][4];
    #pragma unroll
    for (int i = 0; i < 2; i++)
        #pragma unroll
        for (int j = 0; j < 8; j++)
            #pragma unroll
            for (int k = 0; k < 4; k++) acc[i][j][k] = 0.f;

    // ---- prologue: build chunk 0 directly into buffer 0 ----
    {
        float* A0 = sm + A_OFF(0);
        #pragma unroll
        for (int i = 0; i < 4; i++) {
            int row = row0 + i * 32;
            int gk  = kq;
            const float4 p = *(const float4*)(g_PQ + (size_t)sI[row] * 1024 + gk);
            const float4 q = *(const float4*)(g_PQ + (size_t)tI[row] * 1024 + 512 + gk);
            float4 v;
            v.x = tf32r(fmaxf(p.x + q.x + b1s[gk + 0], 0.f));
            v.y = tf32r(fmaxf(p.y + q.y + b1s[gk + 1], 0.f));
            v.z = tf32r(fmaxf(p.z + q.z + b1s[gk + 2], 0.f));
            v.w = tf32r(fmaxf(p.w + q.w + b1s[gk + 3], 0.f));
            *(float4*)(A0 + row * ASTRIDE + kq) = v;
        }
        float* B0 = sm + B_OFF(0);
        #pragma unroll
        for (int i = 0; i < 8; i++) {
            int lin = tid + i * NTHREADS;
            int bk = lin >> 6, bn = lin & 63;
            cp_async16(B0 + bk * BSTRIDE + bn * 4,
                       g_W2R + (size_t)bk * OUT_DIM + bn * 4);
        }
        CP_COMMIT();
        CP_WAIT0();
        __syncthreads();
    }

    // ---- main loop: MMA chunk c, build chunk c+1 ----
    for (int c = 0; c < 8; c++) {
        const int cur = c & 1, nxt = cur ^ 1;
        const float* As = sm + A_OFF(cur);
        const float* Bs = sm + B_OFF(cur);
        float* An = sm + A_OFF(nxt);
        float* Bn = sm + B_OFF(nxt);
        const int kcn = (c + 1) * BK1;
        const bool more = (c < 7);

        float4 pw0, qw0, pw1, qw1;      // wave A prefetch (rows 0..63)
        if (more) {
            pw0 = *(const float4*)(g_PQ + (size_t)sI[row0]      * 1024 + kcn + kq);
            qw0 = *(const float4*)(g_PQ + (size_t)tI[row0]      * 1024 + 512 + kcn + kq);
            pw1 = *(const float4*)(g_PQ + (size_t)sI[row0 + 32] * 1024 + kcn + kq);
            qw1 = *(const float4*)(g_PQ + (size_t)tI[row0 + 32] * 1024 + 512 + kcn + kq);
            #pragma unroll
            for (int i = 0; i < 8; i++) {
                int lin = tid + i * NTHREADS;
                int bk = lin >> 6, bn = lin & 63;
                cp_async16(Bn + bk * BSTRIDE + bn * 4,
                           g_W2R + (size_t)(kcn + bk) * OUT_DIM + bn * 4);
            }
            CP_COMMIT();
        }

        mma_half(As, Bs, acc, wm, wn, g, tg, 0, 4);

        float4 pw2, qw2, pw3, qw3;      // wave B prefetch (rows 64..127)
        if (more) {
            {
                float4 v;
                v.x = tf32r(fmaxf(pw0.x + qw0.x + b1s[kcn + kq + 0], 0.f));
                v.y = tf32r(fmaxf(pw0.y + qw0.y + b1s[kcn + kq + 1], 0.f));
                v.z = tf32r(fmaxf(pw0.z + qw0.z + b1s[kcn + kq + 2], 0.f));
                v.w = tf32r(fmaxf(pw0.w + qw0.w + b1s[kcn + kq + 3], 0.f));
                *(float4*)(An + row0 * ASTRIDE + kq) = v;
                v.x = tf32r(fmaxf(pw1.x + qw1.x + b1s[kcn + kq + 0], 0.f));
                v.y = tf32r(fmaxf(pw1.y + qw1.y + b1s[kcn + kq + 1], 0.f));
                v.z = tf32r(fmaxf(pw1.z + qw1.z + b1s[kcn + kq + 2], 0.f));
                v.w = tf32r(fmaxf(pw1.w + qw1.w + b1s[kcn + kq + 3], 0.f));
                *(float4*)(An + (row0 + 32) * ASTRIDE + kq) = v;
            }
            pw2 = *(const float4*)(g_PQ + (size_t)sI[row0 + 64] * 1024 + kcn + kq);
            qw2 = *(const float4*)(g_PQ + (size_t)tI[row0 + 64] * 1024 + 512 + kcn + kq);
            pw3 = *(const float4*)(g_PQ + (size_t)sI[row0 + 96] * 1024 + kcn + kq);
            qw3 = *(const float4*)(g_PQ + (size_t)tI[row0 + 96] * 1024 + 512 + kcn + kq);
        }

        mma_half(As, Bs, acc, wm, wn, g, tg, 4, 8);

        if (more) {
            float4 v;
            v.x = tf32r(fmaxf(pw2.x + qw2.x + b1s[kcn + kq + 0], 0.f));
            v.y = tf32r(fmaxf(pw2.y + qw2.y + b1s[kcn + kq + 1], 0.f));
            v.z = tf32r(fmaxf(pw2.z + qw2.z + b1s[kcn + kq + 2], 0.f));
            v.w = tf32r(fmaxf(pw2.w + qw2.w + b1s[kcn + kq + 3], 0.f));
            *(float4*)(An + (row0 + 64) * ASTRIDE + kq) = v;
            v.x = tf32r(fmaxf(pw3.x + qw3.x + b1s[kcn + kq + 0], 0.f));
            v.y = tf32r(fmaxf(pw3.y + qw3.y + b1s[kcn + kq + 1], 0.f));
            v.z = tf32r(fmaxf(pw3.z + qw3.z + b1s[kcn + kq + 2], 0.f));
            v.w = tf32r(fmaxf(pw3.w + qw3.w + b1s[kcn + kq + 3], 0.f));
            *(float4*)(An + (row0 + 96) * ASTRIDE + kq) = v;
            CP_WAIT0();
        }
        __syncthreads();
    }

    // ---- epilogue: + b2, store ----
    #pragma unroll
    for (int mt = 0; mt < 2; mt++) {
        int rbase = m0 + wm * 32 + mt * 16;
        #pragma unroll
        for (int nt = 0; nt < 8; nt++) {
            int cb = wn * 64 + nt * 8 + tg * 2;
            float bb0 = b2s[cb], bb1 = b2s[cb + 1];
            float2 v0, v1;
            v0.x = acc[mt][nt][0] + bb0; v0.y = acc[mt][nt][1] + bb1;
            v1.x = acc[mt][nt][2] + bb0; v1.y = acc[mt][nt][3] + bb1;
            *(float2*)(out + (size_t)(rbase + g)     * OUT_DIM + cb) = v0;
            *(float2*)(out + (size_t)(rbase + g + 8) * OUT_DIM + cb) = v1;
        }
    }
}

// ============================================================================
extern "C" void kernel_launch(void* const* d_in, const int* in_sizes, int n_in,
                              void* d_out, int out_size)
{
    (void)out_size;
    const float* x  = (const float*)d_in[0];
    const void*  ei = d_in[1];
    const float* W1 = (const float*)d_in[2];
    const float* b1 = (const float*)d_in[3];
    const float* W2 = (const float*)d_in[4];
    const float* b2 = (const float*)d_in[5];
    for (int i = 0; i < n_in; i++) {
        switch (in_sizes[i]) {
            case N_NODES * IN_DIM:    x  = (const float*)d_in[i]; break;
            case 2 * N_EDGES:         ei = d_in[i];               break;
            case 2 * IN_DIM * HIDDEN: W1 = (const float*)d_in[i]; break;
            case HIDDEN:              b1 = (const float*)d_in[i]; break;
            case HIDDEN * OUT_DIM:    W2 = (const float*)d_in[i]; break;
            case OUT_DIM:             b2 = (const float*)d_in[i]; break;
            default: break;
        }
    }
    float* out = (float*)d_out;

    const size_t smem1 = (size_t)(BM * ASTRIDE + BK1 * BSTRIDE) * sizeof(float);  // 104 KB
    cudaFuncSetAttribute(node_gemm, cudaFuncAttributeMaxDynamicSharedMemorySize, (int)smem1);
    cudaFuncSetAttribute(edge_mlp2, cudaFuncAttributeMaxDynamicSharedMemorySize, (int)DSMEM2);

    prep_edges<<<(2 * N_EDGES + 255) / 256, 256>>>((const int*)ei);
    prep_w2<<<(HIDDEN * OUT_DIM + 255) / 256, 256>>>(W2);

    dim3 grid1((N_NODES + BM - 1) / BM, (2 * HIDDEN) / BN);
    node_gemm<<<grid1, NTHREADS, smem1>>>(x, W1);

    edge_mlp2<<<N_EDGES / BM, NTHREADS, DSMEM2>>>(b1, b2, out);
}